// round 12
// baseline (speedup 1.0000x reference)
#include <cuda_runtime.h>
#include <cuda_fp16.h>
#include <cstdint>

// ---------------------------------------------------------------------------
// ContractiveInvertibleGNN — mma.sync fp16, 256-row CTA split into two
// independent 128-row half-pipelines (warps 0-7 / 8-15) with named barriers.
// ALL weights resident in SMEM (no mid-kernel cp.async). ag stored in-place
// in activation rows (cols 0..32). rel_err ~4.5e-4 (fp16 A and B quant).
// ---------------------------------------------------------------------------

#define PA  272     // activation row pitch (128 fp16 + 16B pad)
#define PF1 80      // fW1 row pitch (32 fp16 + pad), 16B multiple
#define PE  32      // e pitch in floats (128B)
#define PF3 36      // fW3 pitch in floats (144B)

#define OFF_A    0          // 69632 = 256*272
#define OFF_G2   69632      // 34816
#define OFF_F2   104448     // 34816
#define OFF_G3   139264     // 8704
#define OFF_F1   147968     // 10240
#define OFF_F3   158208     // 18432 (128 rows * 144B)
#define OFF_E    176640     // 32768 (256 rows * 128B fp32)
#define OFF_ADJ  209408     // 4224  (33*32*4)
#define OFF_PART 213632     // 2048  (sX early [0,256); partials 2x256 late)
#define SMEM_BYTES 215680

// ---- preformatted fp16 weights ----
__device__ __align__(256) char d_wg2h[34816];  // gW2^T [n128][k128] p272
__device__ __align__(256) char d_wg3h[8704];   // gW3^T [n32][k128]  p272
__device__ __align__(256) char d_wf1h[10240];  // fW1^T [n128][k32]  p80
__device__ __align__(256) char d_wf2h[34816];  // fW2^T [n128][k128] p272
__device__ float d_cg[4096], d_cf[4096], d_wadjT[1024];

__device__ __forceinline__ float lrelu(float x) { return x > 0.f ? x : 0.01f * x; }
__device__ __forceinline__ uint32_t smem_u32(const void* p) {
    uint32_t a;
    asm("{ .reg .u64 t; cvta.to.shared.u64 t, %1; cvt.u32.u64 %0, t; }" : "=r"(a) : "l"(p));
    return a;
}

#define LDSM_X4(r0, r1, r2, r3, addr)                                        \
    asm volatile("ldmatrix.sync.aligned.m8n8.x4.shared.b16 {%0,%1,%2,%3}, [%4];" \
                 : "=r"(r0), "=r"(r1), "=r"(r2), "=r"(r3) : "r"(addr))
#define CP16(d, s) \
    asm volatile("cp.async.ca.shared.global [%0], [%1], 16;" \
                 :: "r"(d), "l"((unsigned long long)__cvta_generic_to_global(s)) : "memory")
#define CP_COMMIT() asm volatile("cp.async.commit_group;" ::: "memory")
#define CP_WAIT0()  asm volatile("cp.async.wait_group 0;" ::: "memory")
#define BARH(id)    asm volatile("bar.sync %0, 256;" :: "r"(id) : "memory")

__device__ __forceinline__ void mma16816(float* c, const uint32_t* a,
                                         uint32_t b0, uint32_t b1) {
    asm volatile("mma.sync.aligned.m16n8k16.row.col.f32.f16.f16.f32 "
                 "{%0,%1,%2,%3}, {%4,%5,%6,%7}, {%8,%9}, {%0,%1,%2,%3};"
                 : "+f"(c[0]), "+f"(c[1]), "+f"(c[2]), "+f"(c[3])
                 : "r"(a[0]), "r"(a[1]), "r"(a[2]), "r"(a[3]), "r"(b0), "r"(b1));
}

// 2-m-tile fp16 GEMM: C += A @ B. C[2][8][4]; only the first 2*NPAIR
// n-tiles per m-tile are touched.
template <int KS, int NPAIR, int AP, int WP>
__device__ __forceinline__ void gemm_2m(uint32_t aH, uint32_t wH,
                                        float C[2][8][4]) {
    #pragma unroll
    for (int k = 0; k < KS; ++k) {
        uint32_t ah[2][4];
        LDSM_X4(ah[0][0], ah[0][1], ah[0][2], ah[0][3], aH + k * 32);
        LDSM_X4(ah[1][0], ah[1][1], ah[1][2], ah[1][3], aH + 16 * AP + k * 32);
        #pragma unroll
        for (int p = 0; p < NPAIR; ++p) {
            uint32_t bh0, bh1, bh2, bh3;
            LDSM_X4(bh0, bh1, bh2, bh3, wH + p * 16 * WP + k * 32);
            #pragma unroll
            for (int t = 0; t < 2; ++t) {
                mma16816(C[t][2 * p],     ah[t], bh0, bh2);
                mma16816(C[t][2 * p + 1], ah[t], bh1, bh3);
            }
        }
    }
}

// ---------------------------------------------------------------------------
__global__ void setup_kernel(const float* __restrict__ W, const float* __restrict__ emb,
                             const float* __restrict__ gW1, const float* __restrict__ gb1,
                             const float* __restrict__ gW2, const float* __restrict__ gW3,
                             const float* __restrict__ fW1, const float* __restrict__ fb1,
                             const float* __restrict__ fW2) {
    int t = blockIdx.x * blockDim.x + threadIdx.x;
    if (t < 4096) {
        int i = t >> 7, a = t & 127;
        float sg = gb1[a], sf = fb1[a];
        #pragma unroll
        for (int e = 0; e < 32; ++e) {
            float em = emb[i * 32 + e];
            sg = fmaf(em, gW1[(32 + e) * 128 + a], sg);
            sf = fmaf(em, fW1[(32 + e) * 128 + a], sf);
        }
        d_cg[t] = sg;
        d_cf[t] = sf;
    }
    if (t < 1024) {
        int i = t >> 5, j = t & 31;
        d_wadjT[t] = (i == j) ? 0.f : W[j * 32 + i];
    }
    if (t < 16384) {                       // gW2^T
        int n = t >> 7, k = t & 127;
        *(__half*)(d_wg2h + n * PA + k * 2) = __float2half_rn(gW2[k * 128 + n]);
    } else if (t < 20480) {                // gW3^T
        int u = t - 16384, n = u >> 7, k = u & 127;
        *(__half*)(d_wg3h + n * PA + k * 2) = __float2half_rn(gW3[k * 32 + n]);
    } else if (t < 24576) {                // fW1[:32]^T
        int u = t - 20480, n = u >> 5, k = u & 31;
        *(__half*)(d_wf1h + n * PF1 + k * 2) = __float2half_rn(fW1[k * 128 + n]);
    } else if (t < 40960) {                // fW2^T
        int u = t - 24576, n = u >> 7, k = u & 127;
        *(__half*)(d_wf2h + n * PA + k * 2) = __float2half_rn(fW2[k * 128 + n]);
    }
}

__device__ __forceinline__ void cpa(uint32_t dst, const void* src, int size, int tid) {
    const char* s = (const char*)src;
    for (int o = tid * 16; o < size; o += 512 * 16) CP16(dst + o, s + o);
}

// ---------------------------------------------------------------------------
__global__ __launch_bounds__(512, 1)
void fused_gnn_kernel(const float* __restrict__ X,
                      const float* __restrict__ gW1,
                      const float* __restrict__ gb2, const float* __restrict__ gb3,
                      const float* __restrict__ fb2,
                      const float* __restrict__ fW3, const float* __restrict__ fb3,
                      float* __restrict__ out) {
    extern __shared__ char sm[];
    const uint32_t smb = smem_u32(sm);
    const int tid = threadIdx.x;
    const int wid = tid >> 5, lane = tid & 31;
    const int half = wid >> 3, hw = wid & 7;
    const int barid = 1 + half;
    const int mw = hw & 3, nh = hw >> 2;
    const int m0 = half * 128 + mw * 32;
    const int t256 = tid & 255;

    char*  sAh  = sm + OFF_A;
    float* sE   = (float*)(sm + OFF_E);
    float* sAdj = (float*)(sm + OFF_ADJ);
    float* sPx  = (float*)(sm + OFF_PART);   // sX early, partials late
    const uint32_t uA = smb + OFF_A;

    const int r0 = m0 + (lane >> 2);
    const int c2 = 2 * (lane & 3);
    const int nc0 = nh * 64;

    const uint32_t aOffA = (uint32_t)((m0 + (lane & 15)) * PA + (lane >> 4) * 16);
    const uint32_t wrow  = (uint32_t)((lane & 7) + 8 * ((lane >> 3) & 1));
    const uint32_t wOffA  = (uint32_t)((nc0 + wrow) * PA + (lane >> 4) * 16);
    const uint32_t wOffG3 = (uint32_t)((nh * 16 + wrow) * PA + (lane >> 4) * 16);
    const uint32_t wOffF1 = (uint32_t)((nc0 + wrow) * PF1 + (lane >> 4) * 16);

    // ---- prologue: ALL weights resident + X/adj staging ----
    cpa(smb + OFF_G2, d_wg2h, 34816, tid);
    cpa(smb + OFF_F2, d_wf2h, 34816, tid);
    cpa(smb + OFF_G3, d_wg3h, 8704, tid);
    cpa(smb + OFF_F1, d_wf1h, 10240, tid);
    for (int idx = tid; idx < 1024; idx += 512) {   // fW3 fp32 repack p144
        int a = idx >> 3, c = idx & 7;
        CP16(smb + OFF_F3 + a * (PF3 * 4) + c * 16, fW3 + a * 32 + c * 4);
    }
    CP_COMMIT();
    if (tid < 256) sPx[tid] = X[blockIdx.x * 256 + tid];
    for (int idx = tid; idx < 1024; idx += 512)
        sAdj[(idx >> 5) * 33 + (idx & 31)] = d_wadjT[idx];
    CP_WAIT0();
    __syncthreads();                                  // B0: everything staged

    // ---- stage 1: h1 per half. thread=(i,kc 0..7), 16 k x 4 batches ----
    {
        int i = t256 & 31, kc = t256 >> 5;            // kc 0..7
        #pragma unroll
        for (int pass = 0; pass < 2; ++pass) {
            float w1v[8], cgv[8];
            #pragma unroll
            for (int u = 0; u < 8; ++u) {
                int k = kc * 16 + pass * 8 + u;
                w1v[u] = __ldg(gW1 + i * 128 + k);
                cgv[u] = __ldg(d_cg + i * 128 + k);
            }
            #pragma unroll
            for (int b = 0; b < 4; ++b) {
                int row = half * 128 + b * 32 + i;
                float xv = sPx[row];
                #pragma unroll
                for (int u = 0; u < 8; u += 2) {
                    int k = kc * 16 + pass * 8 + u;
                    float h0 = lrelu(fmaf(xv, w1v[u],     cgv[u]));
                    float h1v= lrelu(fmaf(xv, w1v[u + 1], cgv[u + 1]));
                    *(__half2*)(sAh + row * PA + k * 2) =
                        __half2(__float2half_rn(h0), __float2half_rn(h1v));
                }
            }
        }
    }
    BARH(barid);                                      // B1: h1 ready (half)

    float C[2][8][4];

    // ---- stage 2: h2 = h1 + lrelu(h1 @ gW2 + gb2) ----
    #pragma unroll
    for (int t = 0; t < 2; ++t)
        #pragma unroll
        for (int n = 0; n < 8; ++n)
            C[t][n][0] = C[t][n][1] = C[t][n][2] = C[t][n][3] = 0.f;
    gemm_2m<8, 4, PA, PA>(uA + aOffA, smb + OFF_G2 + wOffA, C);
    BARH(barid);                                      // B2a: all gemm reads done
    #pragma unroll
    for (int t = 0; t < 2; ++t) {
        int ra = r0 + 16 * t, rb = ra + 8;
        #pragma unroll
        for (int nt = 0; nt < 8; ++nt) {
            int col = nc0 + nt * 8 + c2;
            float b0 = __ldg(gb2 + col), b1 = __ldg(gb2 + col + 1);
            {
                __half2 hh = *(__half2*)(sAh + ra * PA + col * 2);
                float v0 = __half2float(hh.x) + lrelu(C[t][nt][0] + b0);
                float v1 = __half2float(hh.y) + lrelu(C[t][nt][1] + b1);
                *(__half2*)(sAh + ra * PA + col * 2) =
                    __half2(__float2half_rn(v0), __float2half_rn(v1));
            }
            {
                __half2 hh = *(__half2*)(sAh + rb * PA + col * 2);
                float v0 = __half2float(hh.x) + lrelu(C[t][nt][2] + b0);
                float v1 = __half2float(hh.y) + lrelu(C[t][nt][3] + b1);
                *(__half2*)(sAh + rb * PA + col * 2) =
                    __half2(__float2half_rn(v0), __float2half_rn(v1));
            }
        }
    }
    BARH(barid);                                      // B2b: h2 visible

    // ---- stage 3: e = h2 @ gW3 + gb3 (N=32, 1 pair per nh) ----
    #pragma unroll
    for (int t = 0; t < 2; ++t)
        #pragma unroll
        for (int n = 0; n < 2; ++n)
            C[t][n][0] = C[t][n][1] = C[t][n][2] = C[t][n][3] = 0.f;
    gemm_2m<8, 1, PA, PA>(uA + aOffA, smb + OFF_G3 + wOffG3, C);
    #pragma unroll
    for (int t = 0; t < 2; ++t) {
        int ra = r0 + 16 * t, rb = ra + 8;
        #pragma unroll
        for (int nt = 0; nt < 2; ++nt) {
            int col = nh * 16 + nt * 8 + c2;
            float b0 = __ldg(gb3 + col), b1 = __ldg(gb3 + col + 1);
            *(float2*)&sE[ra * PE + col] = make_float2(C[t][nt][0] + b0, C[t][nt][1] + b1);
            *(float2*)&sE[rb * PE + col] = make_float2(C[t][nt][2] + b0, C[t][nt][3] + b1);
        }
    }
    BARH(barid);                                      // B3: sE done, h2 free

    // ---- stage 4: aggregation -> ag fp16, in-place cols 0..32 of sAh ----
    {
        float acc[16];
        #pragma unroll
        for (int d = 0; d < 16; ++d) acc[d] = 0.f;
        int rowH = half * 128 + (t256 >> 1);
        int hf = t256 & 1;
        int i = rowH & 31;
        int bbase = rowH & ~31;
        #pragma unroll 4
        for (int j = 0; j < 32; ++j) {
            float w = sAdj[i * 33 + j];
            const float* er = &sE[(bbase + j) * PE + hf * 16];
            #pragma unroll
            for (int qq = 0; qq < 4; ++qq) {
                float4 ev = *(const float4*)&er[qq * 4];
                acc[qq * 4 + 0] = fmaf(w, ev.x, acc[qq * 4 + 0]);
                acc[qq * 4 + 1] = fmaf(w, ev.y, acc[qq * 4 + 1]);
                acc[qq * 4 + 2] = fmaf(w, ev.z, acc[qq * 4 + 2]);
                acc[qq * 4 + 3] = fmaf(w, ev.w, acc[qq * 4 + 3]);
            }
        }
        #pragma unroll
        for (int d = 0; d < 16; d += 2) {
            int k = (t256 & 1) * 16 + d;
            *(__half2*)(sAh + rowH * PA + k * 2) =
                __half2(__float2half_rn(acc[d]), __float2half_rn(acc[d + 1]));
        }
    }
    BARH(barid);                                      // B4: ag visible

    // ---- stage 5: p1 = lrelu(ag @ fW1 + c_f) (K=32) ----
    #pragma unroll
    for (int t = 0; t < 2; ++t)
        #pragma unroll
        for (int n = 0; n < 8; ++n)
            C[t][n][0] = C[t][n][1] = C[t][n][2] = C[t][n][3] = 0.f;
    gemm_2m<2, 4, PA, PF1>(uA + aOffA, smb + OFF_F1 + wOffF1, C);
    BARH(barid);                                      // B5a: ag reads done
    #pragma unroll
    for (int t = 0; t < 2; ++t) {
        int ra = r0 + 16 * t, rb = ra + 8;
        const float* cfa = d_cf + (ra & 31) * 128;
        const float* cfb = d_cf + (rb & 31) * 128;
        #pragma unroll
        for (int nt = 0; nt < 8; ++nt) {
            int col = nc0 + nt * 8 + c2;
            float v0 = lrelu(C[t][nt][0] + __ldg(cfa + col));
            float v1 = lrelu(C[t][nt][1] + __ldg(cfa + col + 1));
            float v2 = lrelu(C[t][nt][2] + __ldg(cfb + col));
            float v3 = lrelu(C[t][nt][3] + __ldg(cfb + col + 1));
            *(__half2*)(sAh + ra * PA + col * 2) =
                __half2(__float2half_rn(v0), __float2half_rn(v1));
            *(__half2*)(sAh + rb * PA + col * 2) =
                __half2(__float2half_rn(v2), __float2half_rn(v3));
        }
    }
    BARH(barid);                                      // B5b: p1 visible

    // ---- stage 6: p1 @ fW2 ----
    #pragma unroll
    for (int t = 0; t < 2; ++t)
        #pragma unroll
        for (int n = 0; n < 8; ++n)
            C[t][n][0] = C[t][n][1] = C[t][n][2] = C[t][n][3] = 0.f;
    gemm_2m<8, 4, PA, PA>(uA + aOffA, smb + OFF_F2 + wOffA, C);

    // ---- stage 7a: p2 into C (own rows/cols, read-only on sAh) ----
    #pragma unroll
    for (int t = 0; t < 2; ++t) {
        int ra = r0 + 16 * t, rb = ra + 8;
        #pragma unroll
        for (int nt = 0; nt < 8; ++nt) {
            int col = nc0 + nt * 8 + c2;
            float b0 = __ldg(fb2 + col), b1 = __ldg(fb2 + col + 1);
            __half2 hh = *(__half2*)(sAh + ra * PA + col * 2);
            C[t][nt][0] = __half2float(hh.x) + lrelu(C[t][nt][0] + b0);
            C[t][nt][1] = __half2float(hh.y) + lrelu(C[t][nt][1] + b1);
            hh = *(__half2*)(sAh + rb * PA + col * 2);
            C[t][nt][2] = __half2float(hh.x) + lrelu(C[t][nt][2] + b0);
            C[t][nt][3] = __half2float(hh.y) + lrelu(C[t][nt][3] + b1);
        }
    }

    // ---- stage 7b: dot with fW3, reduce, partials ----
    {
        const float* sW3 = (const float*)(sm + OFF_F3);
        float acc[2][2] = {{0.f, 0.f}, {0.f, 0.f}};
        #pragma unroll
        for (int t = 0; t < 2; ++t) {
            int ra = r0 + 16 * t, rb = ra + 8;
            int ia = ra & 31, ib = rb & 31;
            #pragma unroll
            for (int nt = 0; nt < 8; ++nt) {
                int col = nc0 + nt * 8 + c2;
                acc[t][0] = fmaf(C[t][nt][0], sW3[col * PF3 + ia], acc[t][0]);
                acc[t][0] = fmaf(C[t][nt][1], sW3[(col + 1) * PF3 + ia], acc[t][0]);
                acc[t][1] = fmaf(C[t][nt][2], sW3[col * PF3 + ib], acc[t][1]);
                acc[t][1] = fmaf(C[t][nt][3], sW3[(col + 1) * PF3 + ib], acc[t][1]);
            }
        }
        #pragma unroll
        for (int t = 0; t < 2; ++t) {
            acc[t][0] += __shfl_xor_sync(0xffffffffu, acc[t][0], 1);
            acc[t][0] += __shfl_xor_sync(0xffffffffu, acc[t][0], 2);
            acc[t][1] += __shfl_xor_sync(0xffffffffu, acc[t][1], 1);
            acc[t][1] += __shfl_xor_sync(0xffffffffu, acc[t][1], 2);
        }
        BARH(barid);                                  // B6: sX region reusable
        if ((lane & 3) == 0) {
            int rloc = r0 - half * 128;               // 0..127
            #pragma unroll
            for (int t = 0; t < 2; ++t) {
                sPx[half * 256 + nh * 128 + rloc + 16 * t]     = acc[t][0];
                sPx[half * 256 + nh * 128 + rloc + 16 * t + 8] = acc[t][1];
            }
        }
    }
    BARH(barid);                                      // B7: partials visible
    if (t256 < 128) {
        int row = half * 128 + t256;
        out[blockIdx.x * 256 + row] = sPx[half * 256 + t256]
                                    + sPx[half * 256 + 128 + t256]
                                    + __ldg(fb3 + (row & 31));
    }
}

// ---------------------------------------------------------------------------
extern "C" void kernel_launch(void* const* d_in, const int* in_sizes, int n_in,
                              void* d_out, int out_size) {
    const float* X   = (const float*)d_in[0];
    const float* W   = (const float*)d_in[1];
    const float* emb = (const float*)d_in[2];
    const float* gW1 = (const float*)d_in[3];
    const float* gb1 = (const float*)d_in[4];
    const float* gW2 = (const float*)d_in[5];
    const float* gb2 = (const float*)d_in[6];
    const float* gW3 = (const float*)d_in[7];
    const float* gb3 = (const float*)d_in[8];
    const float* fW1 = (const float*)d_in[9];
    const float* fb1 = (const float*)d_in[10];
    const float* fW2 = (const float*)d_in[11];
    const float* fb2 = (const float*)d_in[12];
    const float* fW3 = (const float*)d_in[13];
    const float* fb3 = (const float*)d_in[14];
    float* out = (float*)d_out;

    int B = in_sizes[0] / 32;

    cudaFuncSetAttribute(fused_gnn_kernel,
                         cudaFuncAttributeMaxDynamicSharedMemorySize, SMEM_BYTES);

    setup_kernel<<<160, 256>>>(W, emb, gW1, gb1, gW2, gW3, fW1, fb1, fW2);
    fused_gnn_kernel<<<B / 8, 512, SMEM_BYTES>>>(X, gW1, gb2, gb3, fb2, fW3, fb3, out);
}

// round 13
// speedup vs baseline: 1.0300x; 1.0300x over previous
#include <cuda_runtime.h>
#include <cuda_fp16.h>
#include <cstdint>

// ---------------------------------------------------------------------------
// ContractiveInvertibleGNN — mma.sync fp16, 128-row CTA (4 batches), 256 thr,
// 2 CTAs/SM. Warp (mw 0..3, nh 0..1) owns rows [32mw,32mw+32), cols [64nh,+64).
// SMEM W region time-multiplexed: gW2 -> {E | fW1 | gW3} -> fW2 -> fW3.
// rel_err ~4.5e-4 (fp16 A and B quantization), validated at 1e-3 gate.
// ---------------------------------------------------------------------------

#define PA  272     // activation row pitch (128 fp16 + 16B pad)
#define PG  80      // ag row pitch (32 fp16 + pad)
#define PF1 80      // fW1 row pitch — 16B multiple (ldmatrix)
#define PE  32      // e pitch in floats (128B)
#define PF3 36      // fW3 pitch in floats (144B)

#define OFF_A    0          // 34816 = 128*272
#define OFF_W    34816      // 35328: gW2 -> {E | F1 | G3} -> fW2 -> F3
#define OFF_ADJ  70144      // 4224 (33*32*4)
#define OFF_PART 74368      // 1024 (sX 512B early; partials 2x128 floats late)
#define SMEM_BYTES 75392

#define W_E   0             // 16384 (128 rows * 128B fp32)
#define W_F1  16384         // 10240
#define W_G3  26624         // 8704

// ---- preformatted fp16 weights ----
__device__ __align__(256) char d_wg2h[34816];  // gW2^T [n128][k128] p272
__device__ __align__(256) char d_wg3h[8704];   // gW3^T [n32][k128]  p272
__device__ __align__(256) char d_wf1h[10240];  // fW1^T [n128][k32]  p80
__device__ __align__(256) char d_wf2h[34816];  // fW2^T [n128][k128] p272
__device__ float d_cg[4096], d_cf[4096], d_wadjT[1024];

__device__ __forceinline__ float lrelu(float x) { return x > 0.f ? x : 0.01f * x; }
__device__ __forceinline__ uint32_t smem_u32(const void* p) {
    uint32_t a;
    asm("{ .reg .u64 t; cvta.to.shared.u64 t, %1; cvt.u32.u64 %0, t; }" : "=r"(a) : "l"(p));
    return a;
}

#define LDSM_X4(r0, r1, r2, r3, addr)                                        \
    asm volatile("ldmatrix.sync.aligned.m8n8.x4.shared.b16 {%0,%1,%2,%3}, [%4];" \
                 : "=r"(r0), "=r"(r1), "=r"(r2), "=r"(r3) : "r"(addr))
#define CP16(d, s) \
    asm volatile("cp.async.ca.shared.global [%0], [%1], 16;" \
                 :: "r"(d), "l"((unsigned long long)__cvta_generic_to_global(s)) : "memory")
#define CP_COMMIT() asm volatile("cp.async.commit_group;" ::: "memory")
#define CP_WAIT0()  asm volatile("cp.async.wait_group 0;" ::: "memory")

__device__ __forceinline__ void mma16816(float* c, const uint32_t* a,
                                         uint32_t b0, uint32_t b1) {
    asm volatile("mma.sync.aligned.m16n8k16.row.col.f32.f16.f16.f32 "
                 "{%0,%1,%2,%3}, {%4,%5,%6,%7}, {%8,%9}, {%0,%1,%2,%3};"
                 : "+f"(c[0]), "+f"(c[1]), "+f"(c[2]), "+f"(c[3])
                 : "r"(a[0]), "r"(a[1]), "r"(a[2]), "r"(a[3]), "r"(b0), "r"(b1));
}

// 2-m-tile fp16 GEMM: C += A @ B. C[2][8][4]; only the first 2*NPAIR
// n-tiles per m-tile are touched.
template <int KS, int NPAIR, int AP, int WP>
__device__ __forceinline__ void gemm_2m(uint32_t aH, uint32_t wH,
                                        float C[2][8][4]) {
    #pragma unroll
    for (int k = 0; k < KS; ++k) {
        uint32_t ah[2][4];
        LDSM_X4(ah[0][0], ah[0][1], ah[0][2], ah[0][3], aH + k * 32);
        LDSM_X4(ah[1][0], ah[1][1], ah[1][2], ah[1][3], aH + 16 * AP + k * 32);
        #pragma unroll
        for (int p = 0; p < NPAIR; ++p) {
            uint32_t bh0, bh1, bh2, bh3;
            LDSM_X4(bh0, bh1, bh2, bh3, wH + p * 16 * WP + k * 32);
            #pragma unroll
            for (int t = 0; t < 2; ++t) {
                mma16816(C[t][2 * p],     ah[t], bh0, bh2);
                mma16816(C[t][2 * p + 1], ah[t], bh1, bh3);
            }
        }
    }
}

// ---------------------------------------------------------------------------
__global__ void setup_kernel(const float* __restrict__ W, const float* __restrict__ emb,
                             const float* __restrict__ gW1, const float* __restrict__ gb1,
                             const float* __restrict__ gW2, const float* __restrict__ gW3,
                             const float* __restrict__ fW1, const float* __restrict__ fb1,
                             const float* __restrict__ fW2) {
    int t = blockIdx.x * blockDim.x + threadIdx.x;
    if (t < 4096) {
        int i = t >> 7, a = t & 127;
        float sg = gb1[a], sf = fb1[a];
        #pragma unroll
        for (int e = 0; e < 32; ++e) {
            float em = emb[i * 32 + e];
            sg = fmaf(em, gW1[(32 + e) * 128 + a], sg);
            sf = fmaf(em, fW1[(32 + e) * 128 + a], sf);
        }
        d_cg[t] = sg;
        d_cf[t] = sf;
    }
    if (t < 1024) {
        int i = t >> 5, j = t & 31;
        d_wadjT[t] = (i == j) ? 0.f : W[j * 32 + i];
    }
    if (t < 16384) {                       // gW2^T
        int n = t >> 7, k = t & 127;
        *(__half*)(d_wg2h + n * PA + k * 2) = __float2half_rn(gW2[k * 128 + n]);
    } else if (t < 20480) {                // gW3^T
        int u = t - 16384, n = u >> 7, k = u & 127;
        *(__half*)(d_wg3h + n * PA + k * 2) = __float2half_rn(gW3[k * 32 + n]);
    } else if (t < 24576) {                // fW1[:32]^T
        int u = t - 20480, n = u >> 5, k = u & 31;
        *(__half*)(d_wf1h + n * PF1 + k * 2) = __float2half_rn(fW1[k * 128 + n]);
    } else if (t < 40960) {                // fW2^T
        int u = t - 24576, n = u >> 7, k = u & 127;
        *(__half*)(d_wf2h + n * PA + k * 2) = __float2half_rn(fW2[k * 128 + n]);
    }
}

__device__ __forceinline__ void cpa(uint32_t dst, const void* src, int size, int tid) {
    const char* s = (const char*)src;
    for (int o = tid * 16; o < size; o += 256 * 16) CP16(dst + o, s + o);
}

// ---------------------------------------------------------------------------
__global__ __launch_bounds__(256, 2)
void fused_gnn_kernel(const float* __restrict__ X,
                      const float* __restrict__ gW1,
                      const float* __restrict__ gb2, const float* __restrict__ gb3,
                      const float* __restrict__ fb2,
                      const float* __restrict__ fW3, const float* __restrict__ fb3,
                      float* __restrict__ out) {
    extern __shared__ char sm[];
    const uint32_t smb = smem_u32(sm);
    const int tid = threadIdx.x;
    const int wid = tid >> 5, lane = tid & 31;
    const int mw = wid & 3, nh = wid >> 2;
    const int m0 = mw * 32;
    const int rowH = tid >> 1, hf = tid & 1;

    char*  sAh  = sm + OFF_A;
    float* sE   = (float*)(sm + OFF_W + W_E);
    float* sAdj = (float*)(sm + OFF_ADJ);
    float* sPx  = (float*)(sm + OFF_PART);   // sX early, partials late
    const uint32_t uA = smb + OFF_A;
    const uint32_t uW = smb + OFF_W;

    const int r0 = m0 + (lane >> 2);
    const int c2 = 2 * (lane & 3);
    const int nc0 = nh * 64;

    const uint32_t aOffA = (uint32_t)((m0 + (lane & 15)) * PA + (lane >> 4) * 16);
    const uint32_t aOffG = (uint32_t)((m0 + (lane & 15)) * PG + (lane >> 4) * 16);
    const uint32_t wrow  = (uint32_t)((lane & 7) + 8 * ((lane >> 3) & 1));
    const uint32_t wOffA  = (uint32_t)((nc0 + wrow) * PA + (lane >> 4) * 16);
    const uint32_t wOffG3 = (uint32_t)((nh * 16 + wrow) * PA + (lane >> 4) * 16);
    const uint32_t wOffF1 = (uint32_t)((nc0 + wrow) * PF1 + (lane >> 4) * 16);

    // ---- prologue: gW2 prefetch (G0) + X/adj staging ----
    cpa(uW, d_wg2h, 34816, tid);
    CP_COMMIT();
    if (tid < 128) sPx[tid] = X[blockIdx.x * 128 + tid];
    for (int idx = tid; idx < 1024; idx += 256)
        sAdj[(idx >> 5) * 33 + (idx & 31)] = d_wadjT[idx];
    __syncthreads();                                   // B0: sX visible

    // ---- stage 1: h1. thread = (i, kc 0..7) x 16 k x 4 batches ----
    {
        int i = tid & 31, kc = tid >> 5;               // kc 0..7
        #pragma unroll
        for (int pass = 0; pass < 2; ++pass) {
            float w1v[8], cgv[8];
            #pragma unroll
            for (int u = 0; u < 8; ++u) {
                int k = kc * 16 + pass * 8 + u;
                w1v[u] = __ldg(gW1 + i * 128 + k);
                cgv[u] = __ldg(d_cg + i * 128 + k);
            }
            #pragma unroll
            for (int b = 0; b < 4; ++b) {
                int row = b * 32 + i;
                float xv = sPx[row];
                #pragma unroll
                for (int u = 0; u < 8; u += 2) {
                    int k = kc * 16 + pass * 8 + u;
                    float h0 = lrelu(fmaf(xv, w1v[u],     cgv[u]));
                    float h1v= lrelu(fmaf(xv, w1v[u + 1], cgv[u + 1]));
                    *(__half2*)(sAh + row * PA + k * 2) =
                        __half2(__float2half_rn(h0), __float2half_rn(h1v));
                }
            }
        }
    }
    CP_WAIT0();
    __syncthreads();                                   // B1: h1 + gW2

    float C[2][8][4];

    // ---- stage 2: h2 = h1 + lrelu(h1 @ gW2 + gb2) ----
    #pragma unroll
    for (int t = 0; t < 2; ++t)
        #pragma unroll
        for (int n = 0; n < 8; ++n)
            C[t][n][0] = C[t][n][1] = C[t][n][2] = C[t][n][3] = 0.f;
    gemm_2m<8, 4, PA, PA>(uA + aOffA, uW + wOffA, C);
    __syncthreads();                                   // B2a: gW2 dead
    cpa(uW + W_F1, d_wf1h, 10240, tid);
    cpa(uW + W_G3, d_wg3h, 8704, tid);
    CP_COMMIT();                                       // G1 under epilogue
    #pragma unroll
    for (int t = 0; t < 2; ++t) {
        int ra = r0 + 16 * t, rb = ra + 8;
        #pragma unroll
        for (int nt = 0; nt < 8; ++nt) {
            int col = nc0 + nt * 8 + c2;
            float b0 = __ldg(gb2 + col), b1 = __ldg(gb2 + col + 1);
            {
                __half2 hh = *(__half2*)(sAh + ra * PA + col * 2);
                float v0 = __half2float(hh.x) + lrelu(C[t][nt][0] + b0);
                float v1 = __half2float(hh.y) + lrelu(C[t][nt][1] + b1);
                *(__half2*)(sAh + ra * PA + col * 2) =
                    __half2(__float2half_rn(v0), __float2half_rn(v1));
            }
            {
                __half2 hh = *(__half2*)(sAh + rb * PA + col * 2);
                float v0 = __half2float(hh.x) + lrelu(C[t][nt][2] + b0);
                float v1 = __half2float(hh.y) + lrelu(C[t][nt][3] + b1);
                *(__half2*)(sAh + rb * PA + col * 2) =
                    __half2(__float2half_rn(v0), __float2half_rn(v1));
            }
        }
    }
    CP_WAIT0();
    __syncthreads();                                   // B2b: h2 + G3/F1

    // ---- stage 3: e = h2 @ gW3 + gb3 (N=32 -> 1 pair per nh) ----
    #pragma unroll
    for (int t = 0; t < 2; ++t)
        #pragma unroll
        for (int n = 0; n < 2; ++n)
            C[t][n][0] = C[t][n][1] = C[t][n][2] = C[t][n][3] = 0.f;
    gemm_2m<8, 1, PA, PA>(uA + aOffA, uW + W_G3 + wOffG3, C);
    #pragma unroll
    for (int t = 0; t < 2; ++t) {
        int ra = r0 + 16 * t, rb = ra + 8;
        #pragma unroll
        for (int nt = 0; nt < 2; ++nt) {
            int col = nh * 16 + nt * 8 + c2;
            float b0 = __ldg(gb3 + col), b1 = __ldg(gb3 + col + 1);
            *(float2*)&sE[ra * PE + col] = make_float2(C[t][nt][0] + b0, C[t][nt][1] + b1);
            *(float2*)&sE[rb * PE + col] = make_float2(C[t][nt][2] + b0, C[t][nt][3] + b1);
        }
    }
    __syncthreads();                                   // B3: sE done, h2/A free

    // ---- stage 4: aggregation -> ag fp16 (PG) ----
    {
        float acc[16];
        #pragma unroll
        for (int d = 0; d < 16; ++d) acc[d] = 0.f;
        int i = rowH & 31;
        int bbase = rowH & ~31;
        #pragma unroll 4
        for (int j = 0; j < 32; ++j) {
            float w = sAdj[i * 33 + j];
            const float* er = &sE[(bbase + j) * PE + hf * 16];
            #pragma unroll
            for (int qq = 0; qq < 4; ++qq) {
                float4 ev = *(const float4*)&er[qq * 4];
                acc[qq * 4 + 0] = fmaf(w, ev.x, acc[qq * 4 + 0]);
                acc[qq * 4 + 1] = fmaf(w, ev.y, acc[qq * 4 + 1]);
                acc[qq * 4 + 2] = fmaf(w, ev.z, acc[qq * 4 + 2]);
                acc[qq * 4 + 3] = fmaf(w, ev.w, acc[qq * 4 + 3]);
            }
        }
        #pragma unroll
        for (int d = 0; d < 16; d += 2) {
            int k = hf * 16 + d;
            *(__half2*)(sAh + rowH * PG + k * 2) =
                __half2(__float2half_rn(acc[d]), __float2half_rn(acc[d + 1]));
        }
    }
    __syncthreads();                                   // B4: ag visible

    // ---- stage 5: p1 = lrelu(ag @ fW1 + c_f) (K=32) ----
    #pragma unroll
    for (int t = 0; t < 2; ++t)
        #pragma unroll
        for (int n = 0; n < 8; ++n)
            C[t][n][0] = C[t][n][1] = C[t][n][2] = C[t][n][3] = 0.f;
    gemm_2m<2, 4, PG, PF1>(uA + aOffG, uW + W_F1 + wOffF1, C);
    __syncthreads();                                   // B5a: ag/F1/E dead
    cpa(uW, d_wf2h, 34816, tid);
    CP_COMMIT();                                       // G2 under epilogue
    #pragma unroll
    for (int t = 0; t < 2; ++t) {
        int ra = r0 + 16 * t, rb = ra + 8;
        const float* cfa = d_cf + (ra & 31) * 128;
        const float* cfb = d_cf + (rb & 31) * 128;
        #pragma unroll
        for (int nt = 0; nt < 8; ++nt) {
            int col = nc0 + nt * 8 + c2;
            float v0 = lrelu(C[t][nt][0] + __ldg(cfa + col));
            float v1 = lrelu(C[t][nt][1] + __ldg(cfa + col + 1));
            float v2 = lrelu(C[t][nt][2] + __ldg(cfb + col));
            float v3 = lrelu(C[t][nt][3] + __ldg(cfb + col + 1));
            *(__half2*)(sAh + ra * PA + col * 2) =
                __half2(__float2half_rn(v0), __float2half_rn(v1));
            *(__half2*)(sAh + rb * PA + col * 2) =
                __half2(__float2half_rn(v2), __float2half_rn(v3));
        }
    }
    CP_WAIT0();
    __syncthreads();                                   // B5b: p1 + fW2

    // ---- stage 6: p1 @ fW2 ----
    #pragma unroll
    for (int t = 0; t < 2; ++t)
        #pragma unroll
        for (int n = 0; n < 8; ++n)
            C[t][n][0] = C[t][n][1] = C[t][n][2] = C[t][n][3] = 0.f;
    gemm_2m<8, 4, PA, PA>(uA + aOffA, uW + wOffA, C);
    __syncthreads();                                   // B6a: fW2 dead
    // F3 repack fp32 [a=128][i=32] -> pitch 36 floats
    for (int idx = tid; idx < 1024; idx += 256) {
        int a = idx >> 3, c = idx & 7;
        CP16(uW + a * (PF3 * 4) + c * 16, fW3 + a * 32 + c * 4);
    }
    CP_COMMIT();

    // ---- stage 7a: p2 into C (overlaps F3 flight) ----
    #pragma unroll
    for (int t = 0; t < 2; ++t) {
        int ra = r0 + 16 * t, rb = ra + 8;
        #pragma unroll
        for (int nt = 0; nt < 8; ++nt) {
            int col = nc0 + nt * 8 + c2;
            float b0 = __ldg(fb2 + col), b1 = __ldg(fb2 + col + 1);
            __half2 hh = *(__half2*)(sAh + ra * PA + col * 2);
            C[t][nt][0] = __half2float(hh.x) + lrelu(C[t][nt][0] + b0);
            C[t][nt][1] = __half2float(hh.y) + lrelu(C[t][nt][1] + b1);
            hh = *(__half2*)(sAh + rb * PA + col * 2);
            C[t][nt][2] = __half2float(hh.x) + lrelu(C[t][nt][2] + b0);
            C[t][nt][3] = __half2float(hh.y) + lrelu(C[t][nt][3] + b1);
        }
    }
    CP_WAIT0();
    __syncthreads();                                   // B6b: F3 visible

    // ---- stage 7b: dot with fW3, reduce, partials ----
    {
        const float* sW3 = (const float*)(sm + OFF_W);
        float acc[2][2] = {{0.f, 0.f}, {0.f, 0.f}};
        #pragma unroll
        for (int t = 0; t < 2; ++t) {
            int ra = r0 + 16 * t, rb = ra + 8;
            int ia = ra & 31, ib = rb & 31;
            #pragma unroll
            for (int nt = 0; nt < 8; ++nt) {
                int col = nc0 + nt * 8 + c2;
                acc[t][0] = fmaf(C[t][nt][0], sW3[col * PF3 + ia], acc[t][0]);
                acc[t][0] = fmaf(C[t][nt][1], sW3[(col + 1) * PF3 + ia], acc[t][0]);
                acc[t][1] = fmaf(C[t][nt][2], sW3[col * PF3 + ib], acc[t][1]);
                acc[t][1] = fmaf(C[t][nt][3], sW3[(col + 1) * PF3 + ib], acc[t][1]);
            }
        }
        #pragma unroll
        for (int t = 0; t < 2; ++t) {
            acc[t][0] += __shfl_xor_sync(0xffffffffu, acc[t][0], 1);
            acc[t][0] += __shfl_xor_sync(0xffffffffu, acc[t][0], 2);
            acc[t][1] += __shfl_xor_sync(0xffffffffu, acc[t][1], 1);
            acc[t][1] += __shfl_xor_sync(0xffffffffu, acc[t][1], 2);
        }
        __syncthreads();                               // sPx: sX -> partials
        if ((lane & 3) == 0) {
            #pragma unroll
            for (int t = 0; t < 2; ++t) {
                sPx[nh * 128 + r0 + 16 * t]     = acc[t][0];
                sPx[nh * 128 + r0 + 16 * t + 8] = acc[t][1];
            }
        }
    }
    __syncthreads();                                   // B7
    if (tid < 128)
        out[blockIdx.x * 128 + tid] = sPx[tid] + sPx[128 + tid] + __ldg(fb3 + (tid & 31));
}

// ---------------------------------------------------------------------------
extern "C" void kernel_launch(void* const* d_in, const int* in_sizes, int n_in,
                              void* d_out, int out_size) {
    const float* X   = (const float*)d_in[0];
    const float* W   = (const float*)d_in[1];
    const float* emb = (const float*)d_in[2];
    const float* gW1 = (const float*)d_in[3];
    const float* gb1 = (const float*)d_in[4];
    const float* gW2 = (const float*)d_in[5];
    const float* gb2 = (const float*)d_in[6];
    const float* gW3 = (const float*)d_in[7];
    const float* gb3 = (const float*)d_in[8];
    const float* fW1 = (const float*)d_in[9];
    const float* fb1 = (const float*)d_in[10];
    const float* fW2 = (const float*)d_in[11];
    const float* fb2 = (const float*)d_in[12];
    const float* fW3 = (const float*)d_in[13];
    const float* fb3 = (const float*)d_in[14];
    float* out = (float*)d_out;

    int B = in_sizes[0] / 32;

    cudaFuncSetAttribute(fused_gnn_kernel,
                         cudaFuncAttributeMaxDynamicSharedMemorySize, SMEM_BYTES);

    setup_kernel<<<160, 256>>>(W, emb, gW1, gb1, gW2, gW3, fW1, fb1, fW2);
    fused_gnn_kernel<<<B / 4, 256, SMEM_BYTES>>>(X, gW1, gb2, gb3, fb2, fW3, fb3, out);
}

// round 15
// speedup vs baseline: 1.3260x; 1.2873x over previous
#include <cuda_runtime.h>
#include <cuda_fp16.h>
#include <cstdint>

// ---------------------------------------------------------------------------
// ContractiveInvertibleGNN — mma.sync fp16, 256-row CTA, 512 thr, 16 warps,
// warp (mw 0..7, nh 0..1) tile 32x64. ALL weights resident in disjoint SMEM
// (prologue cp.async, overlapped with h1 generation). R11 execution skeleton.
// rel_err ~4.5e-4 (fp16 A and B quantization).
// ---------------------------------------------------------------------------

#define PA  272     // activation row pitch (128 fp16 + 16B pad)
#define PG  80      // ag row pitch (32 fp16 + pad)
#define PF1 80      // fW1 row pitch — 16B multiple (ldmatrix)
#define PE  32      // e pitch in floats (128B)
#define PF3 36      // fW3 pitch in floats (144B)

#define OFF_A    0          // 69632 = 256*272  (h1/h2, then ag @PG, then p1)
#define OFF_G2   69632      // 34816
#define OFF_F2   104448     // 34816
#define OFF_G3   139264     // 8704
#define OFF_F1   147968     // 10240
#define OFF_F3   158208     // 18432 (128 rows * 144B fp32)
#define OFF_E    176640     // 32768 (256 rows * 128B fp32)
#define OFF_ADJ  209408     // 4224  (33*32*4)
#define OFF_PART 213632     // 2048  (sX early; partials 2x256 floats late)
#define SMEM_BYTES 215680

// ---- preformatted fp16 weights ----
__device__ __align__(256) char d_wg2h[34816];  // gW2^T [n128][k128] p272
__device__ __align__(256) char d_wg3h[8704];   // gW3^T [n32][k128]  p272
__device__ __align__(256) char d_wf1h[10240];  // fW1^T [n128][k32]  p80
__device__ __align__(256) char d_wf2h[34816];  // fW2^T [n128][k128] p272
__device__ float d_cg[4096], d_cf[4096], d_wadjT[1024];

__device__ __forceinline__ float lrelu(float x) { return x > 0.f ? x : 0.01f * x; }
__device__ __forceinline__ uint32_t smem_u32(const void* p) {
    uint32_t a;
    asm("{ .reg .u64 t; cvta.to.shared.u64 t, %1; cvt.u32.u64 %0, t; }" : "=r"(a) : "l"(p));
    return a;
}

#define LDSM_X4(r0, r1, r2, r3, addr)                                        \
    asm volatile("ldmatrix.sync.aligned.m8n8.x4.shared.b16 {%0,%1,%2,%3}, [%4];" \
                 : "=r"(r0), "=r"(r1), "=r"(r2), "=r"(r3) : "r"(addr))
#define CP16(d, s) \
    asm volatile("cp.async.ca.shared.global [%0], [%1], 16;" \
                 :: "r"(d), "l"((unsigned long long)__cvta_generic_to_global(s)) : "memory")
#define CP_COMMIT() asm volatile("cp.async.commit_group;" ::: "memory")
#define CP_WAIT0()  asm volatile("cp.async.wait_group 0;" ::: "memory")

__device__ __forceinline__ void mma16816(float* c, const uint32_t* a,
                                         uint32_t b0, uint32_t b1) {
    asm volatile("mma.sync.aligned.m16n8k16.row.col.f32.f16.f16.f32 "
                 "{%0,%1,%2,%3}, {%4,%5,%6,%7}, {%8,%9}, {%0,%1,%2,%3};"
                 : "+f"(c[0]), "+f"(c[1]), "+f"(c[2]), "+f"(c[3])
                 : "r"(a[0]), "r"(a[1]), "r"(a[2]), "r"(a[3]), "r"(b0), "r"(b1));
}

// 2-m-tile fp16 GEMM: C += A @ B. C[2][8][4]; only the first 2*NPAIR
// n-tiles per m-tile are touched.
template <int KS, int NPAIR, int AP, int WP>
__device__ __forceinline__ void gemm_2m(uint32_t aH, uint32_t wH,
                                        float C[2][8][4]) {
    #pragma unroll
    for (int k = 0; k < KS; ++k) {
        uint32_t ah[2][4];
        LDSM_X4(ah[0][0], ah[0][1], ah[0][2], ah[0][3], aH + k * 32);
        LDSM_X4(ah[1][0], ah[1][1], ah[1][2], ah[1][3], aH + 16 * AP + k * 32);
        #pragma unroll
        for (int p = 0; p < NPAIR; ++p) {
            uint32_t bh0, bh1, bh2, bh3;
            LDSM_X4(bh0, bh1, bh2, bh3, wH + p * 16 * WP + k * 32);
            #pragma unroll
            for (int t = 0; t < 2; ++t) {
                mma16816(C[t][2 * p],     ah[t], bh0, bh2);
                mma16816(C[t][2 * p + 1], ah[t], bh1, bh3);
            }
        }
    }
}

// ---------------------------------------------------------------------------
__global__ void setup_kernel(const float* __restrict__ W, const float* __restrict__ emb,
                             const float* __restrict__ gW1, const float* __restrict__ gb1,
                             const float* __restrict__ gW2, const float* __restrict__ gW3,
                             const float* __restrict__ fW1, const float* __restrict__ fb1,
                             const float* __restrict__ fW2) {
    int t = blockIdx.x * blockDim.x + threadIdx.x;
    if (t < 4096) {
        int i = t >> 7, a = t & 127;
        float sg = gb1[a], sf = fb1[a];
        #pragma unroll
        for (int e = 0; e < 32; ++e) {
            float em = emb[i * 32 + e];
            sg = fmaf(em, gW1[(32 + e) * 128 + a], sg);
            sf = fmaf(em, fW1[(32 + e) * 128 + a], sf);
        }
        d_cg[t] = sg;
        d_cf[t] = sf;
    }
    if (t < 1024) {
        int i = t >> 5, j = t & 31;
        d_wadjT[t] = (i == j) ? 0.f : W[j * 32 + i];
    }
    if (t < 16384) {                       // gW2^T
        int n = t >> 7, k = t & 127;
        *(__half*)(d_wg2h + n * PA + k * 2) = __float2half_rn(gW2[k * 128 + n]);
    } else if (t < 20480) {                // gW3^T
        int u = t - 16384, n = u >> 7, k = u & 127;
        *(__half*)(d_wg3h + n * PA + k * 2) = __float2half_rn(gW3[k * 32 + n]);
    } else if (t < 24576) {                // fW1[:32]^T
        int u = t - 20480, n = u >> 5, k = u & 31;
        *(__half*)(d_wf1h + n * PF1 + k * 2) = __float2half_rn(fW1[k * 128 + n]);
    } else if (t < 40960) {                // fW2^T
        int u = t - 24576, n = u >> 7, k = u & 127;
        *(__half*)(d_wf2h + n * PA + k * 2) = __float2half_rn(fW2[k * 128 + n]);
    }
}

__device__ __forceinline__ void cpa(uint32_t dst, const void* src, int size, int tid) {
    const char* s = (const char*)src;
    for (int o = tid * 16; o < size; o += 512 * 16) CP16(dst + o, s + o);
}

// ---------------------------------------------------------------------------
__global__ __launch_bounds__(512, 1)
void fused_gnn_kernel(const float* __restrict__ X,
                      const float* __restrict__ gW1,
                      const float* __restrict__ gb2, const float* __restrict__ gb3,
                      const float* __restrict__ fb2,
                      const float* __restrict__ fW3, const float* __restrict__ fb3,
                      float* __restrict__ out) {
    extern __shared__ char sm[];
    const uint32_t smb = smem_u32(sm);
    const int tid = threadIdx.x;
    const int wid = tid >> 5, lane = tid & 31;
    const int mw = wid & 7, nh = wid >> 3;
    const int m0 = mw * 32;
    const int rowH = tid >> 1, hf = tid & 1;

    char*  sAh  = sm + OFF_A;
    float* sE   = (float*)(sm + OFF_E);
    float* sAdj = (float*)(sm + OFF_ADJ);
    float* sPx  = (float*)(sm + OFF_PART);   // sX early, partials late
    const uint32_t uA = smb + OFF_A;

    const int r0 = m0 + (lane >> 2);
    const int c2 = 2 * (lane & 3);
    const int nc0 = nh * 64;

    const uint32_t aOffA = (uint32_t)((m0 + (lane & 15)) * PA + (lane >> 4) * 16);
    const uint32_t aOffG = (uint32_t)((m0 + (lane & 15)) * PG + (lane >> 4) * 16);
    const uint32_t wrow  = (uint32_t)((lane & 7) + 8 * ((lane >> 3) & 1));
    const uint32_t wOffA  = (uint32_t)((nc0 + wrow) * PA + (lane >> 4) * 16);
    const uint32_t wOffG3 = (uint32_t)((nh * 16 + wrow) * PA + (lane >> 4) * 16);
    const uint32_t wOffF1 = (uint32_t)((nc0 + wrow) * PF1 + (lane >> 4) * 16);

    // ---- prologue: ALL weights resident (one group) + X/adj staging ----
    cpa(smb + OFF_G2, d_wg2h, 34816, tid);
    cpa(smb + OFF_F2, d_wf2h, 34816, tid);
    cpa(smb + OFF_G3, d_wg3h, 8704, tid);
    cpa(smb + OFF_F1, d_wf1h, 10240, tid);
    for (int idx = tid; idx < 1024; idx += 512) {   // fW3 fp32 repack p144
        int a = idx >> 3, c = idx & 7;
        CP16(smb + OFF_F3 + a * (PF3 * 4) + c * 16, fW3 + a * 32 + c * 4);
    }
    CP_COMMIT();
    if (tid < 256) sPx[tid] = X[blockIdx.x * 256 + tid];
    for (int idx = tid; idx < 1024; idx += 512)
        sAdj[(idx >> 5) * 33 + (idx & 31)] = d_wadjT[idx];
    __syncthreads();                                   // B0: sX visible

    // ---- stage 1: h1. thread = (i, kc 0..15) x 8 batches (overlaps cp) ----
    {
        int i = tid & 31, kc = tid >> 5;               // kc 0..15
        const float4* w4 = (const float4*)(gW1 + i * 128 + kc * 8);
        const float4* c4 = (const float4*)(d_cg + i * 128 + kc * 8);
        float4 wa = __ldg(w4), wb = __ldg(w4 + 1);
        float4 ca = __ldg(c4), cb = __ldg(c4 + 1);
        float w1v[8] = {wa.x, wa.y, wa.z, wa.w, wb.x, wb.y, wb.z, wb.w};
        float cgv[8] = {ca.x, ca.y, ca.z, ca.w, cb.x, cb.y, cb.z, cb.w};
        #pragma unroll
        for (int b = 0; b < 8; ++b) {
            int row = b * 32 + i;
            float xv = sPx[row];
            #pragma unroll
            for (int u = 0; u < 8; u += 2) {
                int k = kc * 8 + u;
                float h0 = lrelu(fmaf(xv, w1v[u],     cgv[u]));
                float h1v= lrelu(fmaf(xv, w1v[u + 1], cgv[u + 1]));
                *(__half2*)(sAh + row * PA + k * 2) =
                    __half2(__float2half_rn(h0), __float2half_rn(h1v));
            }
        }
    }
    CP_WAIT0();
    __syncthreads();                                   // B1: h1 + all weights

    float C[2][8][4];

    // ---- stage 2: h2 = h1 + lrelu(h1 @ gW2 + gb2) ----
    #pragma unroll
    for (int t = 0; t < 2; ++t)
        #pragma unroll
        for (int n = 0; n < 8; ++n)
            C[t][n][0] = C[t][n][1] = C[t][n][2] = C[t][n][3] = 0.f;
    gemm_2m<8, 4, PA, PA>(uA + aOffA, smb + OFF_G2 + wOffA, C);
    __syncthreads();                                   // B2a: A reads done
    #pragma unroll
    for (int t = 0; t < 2; ++t) {
        int ra = r0 + 16 * t, rb = ra + 8;
        #pragma unroll
        for (int nt = 0; nt < 8; ++nt) {
            int col = nc0 + nt * 8 + c2;
            float b0 = __ldg(gb2 + col), b1 = __ldg(gb2 + col + 1);
            {
                __half2 hh = *(__half2*)(sAh + ra * PA + col * 2);
                float v0 = __half2float(hh.x) + lrelu(C[t][nt][0] + b0);
                float v1 = __half2float(hh.y) + lrelu(C[t][nt][1] + b1);
                *(__half2*)(sAh + ra * PA + col * 2) =
                    __half2(__float2half_rn(v0), __float2half_rn(v1));
            }
            {
                __half2 hh = *(__half2*)(sAh + rb * PA + col * 2);
                float v0 = __half2float(hh.x) + lrelu(C[t][nt][2] + b0);
                float v1 = __half2float(hh.y) + lrelu(C[t][nt][3] + b1);
                *(__half2*)(sAh + rb * PA + col * 2) =
                    __half2(__float2half_rn(v0), __float2half_rn(v1));
            }
        }
    }
    __syncthreads();                                   // B2b: h2 visible

    // ---- stage 3: e = h2 @ gW3 + gb3 (N=32 -> 1 pair per nh) ----
    #pragma unroll
    for (int t = 0; t < 2; ++t)
        #pragma unroll
        for (int n = 0; n < 2; ++n)
            C[t][n][0] = C[t][n][1] = C[t][n][2] = C[t][n][3] = 0.f;
    gemm_2m<8, 1, PA, PA>(uA + aOffA, smb + OFF_G3 + wOffG3, C);
    #pragma unroll
    for (int t = 0; t < 2; ++t) {
        int ra = r0 + 16 * t, rb = ra + 8;
        #pragma unroll
        for (int nt = 0; nt < 2; ++nt) {
            int col = nh * 16 + nt * 8 + c2;
            float b0 = __ldg(gb3 + col), b1 = __ldg(gb3 + col + 1);
            *(float2*)&sE[ra * PE + col] = make_float2(C[t][nt][0] + b0, C[t][nt][1] + b1);
            *(float2*)&sE[rb * PE + col] = make_float2(C[t][nt][2] + b0, C[t][nt][3] + b1);
        }
    }
    __syncthreads();                                   // B3: sE done, h2/A free

    // ---- stage 4: aggregation -> ag fp16 (PG pitch, into A region) ----
    {
        float acc[16];
        #pragma unroll
        for (int d = 0; d < 16; ++d) acc[d] = 0.f;
        int i = rowH & 31;
        int bbase = rowH & ~31;
        #pragma unroll 4
        for (int j = 0; j < 32; ++j) {
            float w = sAdj[i * 33 + j];
            const float* er = &sE[(bbase + j) * PE + hf * 16];
            #pragma unroll
            for (int qq = 0; qq < 4; ++qq) {
                float4 ev = *(const float4*)&er[qq * 4];
                acc[qq * 4 + 0] = fmaf(w, ev.x, acc[qq * 4 + 0]);
                acc[qq * 4 + 1] = fmaf(w, ev.y, acc[qq * 4 + 1]);
                acc[qq * 4 + 2] = fmaf(w, ev.z, acc[qq * 4 + 2]);
                acc[qq * 4 + 3] = fmaf(w, ev.w, acc[qq * 4 + 3]);
            }
        }
        #pragma unroll
        for (int d = 0; d < 16; d += 2) {
            int k = hf * 16 + d;
            *(__half2*)(sAh + rowH * PG + k * 2) =
                __half2(__float2half_rn(acc[d]), __float2half_rn(acc[d + 1]));
        }
    }
    __syncthreads();                                   // B4: ag visible

    // ---- stage 5: p1 = lrelu(ag @ fW1 + c_f) (K=32) ----
    #pragma unroll
    for (int t = 0; t < 2; ++t)
        #pragma unroll
        for (int n = 0; n < 8; ++n)
            C[t][n][0] = C[t][n][1] = C[t][n][2] = C[t][n][3] = 0.f;
    gemm_2m<2, 4, PG, PF1>(uA + aOffG, smb + OFF_F1 + wOffF1, C);
    __syncthreads();                                   // B5a: ag reads done
    #pragma unroll
    for (int t = 0; t < 2; ++t) {
        int ra = r0 + 16 * t, rb = ra + 8;
        const float* cfa = d_cf + (ra & 31) * 128;
        const float* cfb = d_cf + (rb & 31) * 128;
        #pragma unroll
        for (int nt = 0; nt < 8; ++nt) {
            int col = nc0 + nt * 8 + c2;
            float v0 = lrelu(C[t][nt][0] + __ldg(cfa + col));
            float v1 = lrelu(C[t][nt][1] + __ldg(cfa + col + 1));
            float v2 = lrelu(C[t][nt][2] + __ldg(cfb + col));
            float v3 = lrelu(C[t][nt][3] + __ldg(cfb + col + 1));
            *(__half2*)(sAh + ra * PA + col * 2) =
                __half2(__float2half_rn(v0), __float2half_rn(v1));
            *(__half2*)(sAh + rb * PA + col * 2) =
                __half2(__float2half_rn(v2), __float2half_rn(v3));
        }
    }
    __syncthreads();                                   // B5b: p1 visible

    // ---- stage 6: p1 @ fW2 ----
    #pragma unroll
    for (int t = 0; t < 2; ++t)
        #pragma unroll
        for (int n = 0; n < 8; ++n)
            C[t][n][0] = C[t][n][1] = C[t][n][2] = C[t][n][3] = 0.f;
    gemm_2m<8, 4, PA, PA>(uA + aOffA, smb + OFF_F2 + wOffA, C);

    // ---- stage 7a: p2 into C (read-only on sAh, no barrier needed) ----
    #pragma unroll
    for (int t = 0; t < 2; ++t) {
        int ra = r0 + 16 * t, rb = ra + 8;
        #pragma unroll
        for (int nt = 0; nt < 8; ++nt) {
            int col = nc0 + nt * 8 + c2;
            float b0 = __ldg(fb2 + col), b1 = __ldg(fb2 + col + 1);
            __half2 hh = *(__half2*)(sAh + ra * PA + col * 2);
            C[t][nt][0] = __half2float(hh.x) + lrelu(C[t][nt][0] + b0);
            C[t][nt][1] = __half2float(hh.y) + lrelu(C[t][nt][1] + b1);
            hh = *(__half2*)(sAh + rb * PA + col * 2);
            C[t][nt][2] = __half2float(hh.x) + lrelu(C[t][nt][2] + b0);
            C[t][nt][3] = __half2float(hh.y) + lrelu(C[t][nt][3] + b1);
        }
    }

    // ---- stage 7b: dot with fW3 (resident), reduce, partials ----
    {
        const float* sW3 = (const float*)(sm + OFF_F3);
        float acc[2][2] = {{0.f, 0.f}, {0.f, 0.f}};
        #pragma unroll
        for (int t = 0; t < 2; ++t) {
            int ra = r0 + 16 * t, rb = ra + 8;
            int ia = ra & 31, ib = rb & 31;
            #pragma unroll
            for (int nt = 0; nt < 8; ++nt) {
                int col = nc0 + nt * 8 + c2;
                acc[t][0] = fmaf(C[t][nt][0], sW3[col * PF3 + ia], acc[t][0]);
                acc[t][0] = fmaf(C[t][nt][1], sW3[(col + 1) * PF3 + ia], acc[t][0]);
                acc[t][1] = fmaf(C[t][nt][2], sW3[col * PF3 + ib], acc[t][1]);
                acc[t][1] = fmaf(C[t][nt][3], sW3[(col + 1) * PF3 + ib], acc[t][1]);
            }
        }
        #pragma unroll
        for (int t = 0; t < 2; ++t) {
            acc[t][0] += __shfl_xor_sync(0xffffffffu, acc[t][0], 1);
            acc[t][0] += __shfl_xor_sync(0xffffffffu, acc[t][0], 2);
            acc[t][1] += __shfl_xor_sync(0xffffffffu, acc[t][1], 1);
            acc[t][1] += __shfl_xor_sync(0xffffffffu, acc[t][1], 2);
        }
        __syncthreads();                               // B6: sPx reusable
        if ((lane & 3) == 0) {
            #pragma unroll
            for (int t = 0; t < 2; ++t) {
                sPx[nh * 256 + r0 + 16 * t]     = acc[t][0];
                sPx[nh * 256 + r0 + 16 * t + 8] = acc[t][1];
            }
        }
    }
    __syncthreads();                                   // B7: partials visible
    if (tid < 256)
        out[blockIdx.x * 256 + tid] = sPx[tid] + sPx[256 + tid] + __ldg(fb3 + (tid & 31));
}

// ---------------------------------------------------------------------------
extern "C" void kernel_launch(void* const* d_in, const int* in_sizes, int n_in,
                              void* d_out, int out_size) {
    const float* X   = (const float*)d_in[0];
    const float* W   = (const float*)d_in[1];
    const float* emb = (const float*)d_in[2];
    const float* gW1 = (const float*)d_in[3];
    const float* gb1 = (const float*)d_in[4];
    const float* gW2 = (const float*)d_in[5];
    const float* gb2 = (const float*)d_in[6];
    const float* gW3 = (const float*)d_in[7];
    const float* gb3 = (const float*)d_in[8];
    const float* fW1 = (const float*)d_in[9];
    const float* fb1 = (const float*)d_in[10];
    const float* fW2 = (const float*)d_in[11];
    const float* fb2 = (const float*)d_in[12];
    const float* fW3 = (const float*)d_in[13];
    const float* fb3 = (const float*)d_in[14];
    float* out = (float*)d_out;

    int B = in_sizes[0] / 32;

    cudaFuncSetAttribute(fused_gnn_kernel,
                         cudaFuncAttributeMaxDynamicSharedMemorySize, SMEM_BYTES);

    setup_kernel<<<160, 256>>>(W, emb, gW1, gb1, gW2, gW3, fW1, fb1, fW2);
    fused_gnn_kernel<<<B / 8, 512, SMEM_BYTES>>>(X, gW1, gb2, gb3, fb2, fW3, fb3, out);
}

// round 17
// speedup vs baseline: 1.3359x; 1.0075x over previous
#include <cuda_runtime.h>
#include <cuda_fp16.h>
#include <cstdint>

// ---------------------------------------------------------------------------
// ContractiveInvertibleGNN — mma.sync fp16, 256-row CTA, 512 thr, 16 warps,
// warp (mw 0..7, nh 0..1) tile 32x64. ALL weights resident in SMEM.
// Pair-local sync points (B2a/B2b/B5b) use named barriers over the 2 warps
// sharing an m-slab (bar.sync 1+mw, 64); cross-pair stages keep __syncthreads.
// rel_err ~4.5e-4 (fp16 A and B quantization).
// ---------------------------------------------------------------------------

#define PA  272     // activation row pitch (128 fp16 + 16B pad)
#define PG  80      // ag row pitch (32 fp16 + pad)
#define PF1 80      // fW1 row pitch — 16B multiple (ldmatrix)
#define PE  32      // e pitch in floats (128B)
#define PF3 36      // fW3 pitch in floats (144B)

#define OFF_A    0          // 69632 = 256*272  (h1/h2, then ag @PG, then p1)
#define OFF_G2   69632      // 34816
#define OFF_F2   104448     // 34816
#define OFF_G3   139264     // 8704
#define OFF_F1   147968     // 10240
#define OFF_F3   158208     // 18432 (128 rows * 144B fp32)
#define OFF_E    176640     // 32768 (256 rows * 128B fp32)
#define OFF_ADJ  209408     // 4224  (33*32*4)
#define OFF_PART 213632     // 2048  (sX early; partials 2x256 floats late)
#define SMEM_BYTES 215680

// ---- preformatted fp16 weights ----
__device__ __align__(256) char d_wg2h[34816];  // gW2^T [n128][k128] p272
__device__ __align__(256) char d_wg3h[8704];   // gW3^T [n32][k128]  p272
__device__ __align__(256) char d_wf1h[10240];  // fW1^T [n128][k32]  p80
__device__ __align__(256) char d_wf2h[34816];  // fW2^T [n128][k128] p272
__device__ float d_cg[4096], d_cf[4096], d_wadjT[1024];

__device__ __forceinline__ float lrelu(float x) { return x > 0.f ? x : 0.01f * x; }
__device__ __forceinline__ uint32_t smem_u32(const void* p) {
    uint32_t a;
    asm("{ .reg .u64 t; cvta.to.shared.u64 t, %1; cvt.u32.u64 %0, t; }" : "=r"(a) : "l"(p));
    return a;
}

#define LDSM_X4(r0, r1, r2, r3, addr)                                        \
    asm volatile("ldmatrix.sync.aligned.m8n8.x4.shared.b16 {%0,%1,%2,%3}, [%4];" \
                 : "=r"(r0), "=r"(r1), "=r"(r2), "=r"(r3) : "r"(addr))
#define CP16(d, s) \
    asm volatile("cp.async.ca.shared.global [%0], [%1], 16;" \
                 :: "r"(d), "l"((unsigned long long)__cvta_generic_to_global(s)) : "memory")
#define CP_COMMIT() asm volatile("cp.async.commit_group;" ::: "memory")
#define CP_WAIT0()  asm volatile("cp.async.wait_group 0;" ::: "memory")
#define BARP(id)    asm volatile("bar.sync %0, 64;" :: "r"(id) : "memory")

__device__ __forceinline__ void mma16816(float* c, const uint32_t* a,
                                         uint32_t b0, uint32_t b1) {
    asm volatile("mma.sync.aligned.m16n8k16.row.col.f32.f16.f16.f32 "
                 "{%0,%1,%2,%3}, {%4,%5,%6,%7}, {%8,%9}, {%0,%1,%2,%3};"
                 : "+f"(c[0]), "+f"(c[1]), "+f"(c[2]), "+f"(c[3])
                 : "r"(a[0]), "r"(a[1]), "r"(a[2]), "r"(a[3]), "r"(b0), "r"(b1));
}

// 2-m-tile fp16 GEMM: C += A @ B. C[2][8][4]; only the first 2*NPAIR
// n-tiles per m-tile are touched.
template <int KS, int NPAIR, int AP, int WP>
__device__ __forceinline__ void gemm_2m(uint32_t aH, uint32_t wH,
                                        float C[2][8][4]) {
    #pragma unroll
    for (int k = 0; k < KS; ++k) {
        uint32_t ah[2][4];
        LDSM_X4(ah[0][0], ah[0][1], ah[0][2], ah[0][3], aH + k * 32);
        LDSM_X4(ah[1][0], ah[1][1], ah[1][2], ah[1][3], aH + 16 * AP + k * 32);
        #pragma unroll
        for (int p = 0; p < NPAIR; ++p) {
            uint32_t bh0, bh1, bh2, bh3;
            LDSM_X4(bh0, bh1, bh2, bh3, wH + p * 16 * WP + k * 32);
            #pragma unroll
            for (int t = 0; t < 2; ++t) {
                mma16816(C[t][2 * p],     ah[t], bh0, bh2);
                mma16816(C[t][2 * p + 1], ah[t], bh1, bh3);
            }
        }
    }
}

// ---------------------------------------------------------------------------
__global__ void setup_kernel(const float* __restrict__ W, const float* __restrict__ emb,
                             const float* __restrict__ gW1, const float* __restrict__ gb1,
                             const float* __restrict__ gW2, const float* __restrict__ gW3,
                             const float* __restrict__ fW1, const float* __restrict__ fb1,
                             const float* __restrict__ fW2) {
    int t = blockIdx.x * blockDim.x + threadIdx.x;
    if (t < 4096) {
        int i = t >> 7, a = t & 127;
        float sg = gb1[a], sf = fb1[a];
        #pragma unroll
        for (int e = 0; e < 32; ++e) {
            float em = emb[i * 32 + e];
            sg = fmaf(em, gW1[(32 + e) * 128 + a], sg);
            sf = fmaf(em, fW1[(32 + e) * 128 + a], sf);
        }
        d_cg[t] = sg;
        d_cf[t] = sf;
    }
    if (t < 1024) {
        int i = t >> 5, j = t & 31;
        d_wadjT[t] = (i == j) ? 0.f : W[j * 32 + i];
    }
    if (t < 16384) {                       // gW2^T
        int n = t >> 7, k = t & 127;
        *(__half*)(d_wg2h + n * PA + k * 2) = __float2half_rn(gW2[k * 128 + n]);
    } else if (t < 20480) {                // gW3^T
        int u = t - 16384, n = u >> 7, k = u & 127;
        *(__half*)(d_wg3h + n * PA + k * 2) = __float2half_rn(gW3[k * 32 + n]);
    } else if (t < 24576) {                // fW1[:32]^T
        int u = t - 20480, n = u >> 5, k = u & 31;
        *(__half*)(d_wf1h + n * PF1 + k * 2) = __float2half_rn(fW1[k * 128 + n]);
    } else if (t < 40960) {                // fW2^T
        int u = t - 24576, n = u >> 7, k = u & 127;
        *(__half*)(d_wf2h + n * PA + k * 2) = __float2half_rn(fW2[k * 128 + n]);
    }
}

__device__ __forceinline__ void cpa(uint32_t dst, const void* src, int size, int tid) {
    const char* s = (const char*)src;
    for (int o = tid * 16; o < size; o += 512 * 16) CP16(dst + o, s + o);
}

// ---------------------------------------------------------------------------
__global__ __launch_bounds__(512, 1)
void fused_gnn_kernel(const float* __restrict__ X,
                      const float* __restrict__ gW1,
                      const float* __restrict__ gb2, const float* __restrict__ gb3,
                      const float* __restrict__ fb2,
                      const float* __restrict__ fW3, const float* __restrict__ fb3,
                      float* __restrict__ out) {
    extern __shared__ char sm[];
    const uint32_t smb = smem_u32(sm);
    const int tid = threadIdx.x;
    const int wid = tid >> 5, lane = tid & 31;
    const int mw = wid & 7, nh = wid >> 3;
    const int m0 = mw * 32;
    const int pairid = 1 + mw;               // named barrier id for the m-slab pair
    const int rowH = tid >> 1, hf = tid & 1;

    char*  sAh  = sm + OFF_A;
    float* sE   = (float*)(sm + OFF_E);
    float* sAdj = (float*)(sm + OFF_ADJ);
    float* sPx  = (float*)(sm + OFF_PART);   // sX early, partials late
    const uint32_t uA = smb + OFF_A;

    const int r0 = m0 + (lane >> 2);
    const int c2 = 2 * (lane & 3);
    const int nc0 = nh * 64;

    const uint32_t aOffA = (uint32_t)((m0 + (lane & 15)) * PA + (lane >> 4) * 16);
    const uint32_t aOffG = (uint32_t)((m0 + (lane & 15)) * PG + (lane >> 4) * 16);
    const uint32_t wrow  = (uint32_t)((lane & 7) + 8 * ((lane >> 3) & 1));
    const uint32_t wOffA  = (uint32_t)((nc0 + wrow) * PA + (lane >> 4) * 16);
    const uint32_t wOffG3 = (uint32_t)((nh * 16 + wrow) * PA + (lane >> 4) * 16);
    const uint32_t wOffF1 = (uint32_t)((nc0 + wrow) * PF1 + (lane >> 4) * 16);

    // ---- prologue: ALL weights resident (one group) + X/adj staging ----
    cpa(smb + OFF_G2, d_wg2h, 34816, tid);
    cpa(smb + OFF_F2, d_wf2h, 34816, tid);
    cpa(smb + OFF_G3, d_wg3h, 8704, tid);
    cpa(smb + OFF_F1, d_wf1h, 10240, tid);
    for (int idx = tid; idx < 1024; idx += 512) {   // fW3 fp32 repack p144
        int a = idx >> 3, c = idx & 7;
        CP16(smb + OFF_F3 + a * (PF3 * 4) + c * 16, fW3 + a * 32 + c * 4);
    }
    CP_COMMIT();
    if (tid < 256) sPx[tid] = X[blockIdx.x * 256 + tid];
    for (int idx = tid; idx < 1024; idx += 512)
        sAdj[(idx >> 5) * 33 + (idx & 31)] = d_wadjT[idx];
    __syncthreads();                                   // B0: sX visible

    // ---- stage 1: h1. thread = (i, kc 0..15) x 8 batches (overlaps cp) ----
    {
        int i = tid & 31, kc = tid >> 5;               // kc 0..15
        const float4* w4 = (const float4*)(gW1 + i * 128 + kc * 8);
        const float4* c4 = (const float4*)(d_cg + i * 128 + kc * 8);
        float4 wa = __ldg(w4), wb = __ldg(w4 + 1);
        float4 ca = __ldg(c4), cb = __ldg(c4 + 1);
        float w1v[8] = {wa.x, wa.y, wa.z, wa.w, wb.x, wb.y, wb.z, wb.w};
        float cgv[8] = {ca.x, ca.y, ca.z, ca.w, cb.x, cb.y, cb.z, cb.w};
        #pragma unroll
        for (int b = 0; b < 8; ++b) {
            int row = b * 32 + i;
            float xv = sPx[row];
            #pragma unroll
            for (int u = 0; u < 8; u += 2) {
                int k = kc * 8 + u;
                float h0 = lrelu(fmaf(xv, w1v[u],     cgv[u]));
                float h1v= lrelu(fmaf(xv, w1v[u + 1], cgv[u + 1]));
                *(__half2*)(sAh + row * PA + k * 2) =
                    __half2(__float2half_rn(h0), __float2half_rn(h1v));
            }
        }
    }
    CP_WAIT0();
    __syncthreads();                                   // B1: h1 + all weights

    float C[2][8][4];

    // ---- stage 2: h2 = h1 + lrelu(h1 @ gW2 + gb2) ----
    #pragma unroll
    for (int t = 0; t < 2; ++t)
        #pragma unroll
        for (int n = 0; n < 8; ++n)
            C[t][n][0] = C[t][n][1] = C[t][n][2] = C[t][n][3] = 0.f;
    gemm_2m<8, 4, PA, PA>(uA + aOffA, smb + OFF_G2 + wOffA, C);
    BARP(pairid);                                      // B2a: pair gemm reads done
    #pragma unroll
    for (int t = 0; t < 2; ++t) {
        int ra = r0 + 16 * t, rb = ra + 8;
        #pragma unroll
        for (int nt = 0; nt < 8; ++nt) {
            int col = nc0 + nt * 8 + c2;
            float b0 = __ldg(gb2 + col), b1 = __ldg(gb2 + col + 1);
            {
                __half2 hh = *(__half2*)(sAh + ra * PA + col * 2);
                float v0 = __half2float(hh.x) + lrelu(C[t][nt][0] + b0);
                float v1 = __half2float(hh.y) + lrelu(C[t][nt][1] + b1);
                *(__half2*)(sAh + ra * PA + col * 2) =
                    __half2(__float2half_rn(v0), __float2half_rn(v1));
            }
            {
                __half2 hh = *(__half2*)(sAh + rb * PA + col * 2);
                float v0 = __half2float(hh.x) + lrelu(C[t][nt][2] + b0);
                float v1 = __half2float(hh.y) + lrelu(C[t][nt][3] + b1);
                *(__half2*)(sAh + rb * PA + col * 2) =
                    __half2(__float2half_rn(v0), __float2half_rn(v1));
            }
        }
    }
    BARP(pairid);                                      // B2b: h2 visible in pair

    // ---- stage 3: e = h2 @ gW3 + gb3 (N=32 -> 1 pair per nh) ----
    #pragma unroll
    for (int t = 0; t < 2; ++t)
        #pragma unroll
        for (int n = 0; n < 2; ++n)
            C[t][n][0] = C[t][n][1] = C[t][n][2] = C[t][n][3] = 0.f;
    gemm_2m<8, 1, PA, PA>(uA + aOffA, smb + OFF_G3 + wOffG3, C);
    #pragma unroll
    for (int t = 0; t < 2; ++t) {
        int ra = r0 + 16 * t, rb = ra + 8;
        #pragma unroll
        for (int nt = 0; nt < 2; ++nt) {
            int col = nh * 16 + nt * 8 + c2;
            float b0 = __ldg(gb3 + col), b1 = __ldg(gb3 + col + 1);
            *(float2*)&sE[ra * PE + col] = make_float2(C[t][nt][0] + b0, C[t][nt][1] + b1);
            *(float2*)&sE[rb * PE + col] = make_float2(C[t][nt][2] + b0, C[t][nt][3] + b1);
        }
    }
    __syncthreads();                                   // B3: sE done, h2/A free

    // ---- stage 4: aggregation -> ag fp16 (PG pitch, into A region) ----
    {
        float acc[16];
        #pragma unroll
        for (int d = 0; d < 16; ++d) acc[d] = 0.f;
        int i = rowH & 31;
        int bbase = rowH & ~31;
        #pragma unroll 4
        for (int j = 0; j < 32; ++j) {
            float w = sAdj[i * 33 + j];
            const float* er = &sE[(bbase + j) * PE + hf * 16];
            #pragma unroll
            for (int qq = 0; qq < 4; ++qq) {
                float4 ev = *(const float4*)&er[qq * 4];
                acc[qq * 4 + 0] = fmaf(w, ev.x, acc[qq * 4 + 0]);
                acc[qq * 4 + 1] = fmaf(w, ev.y, acc[qq * 4 + 1]);
                acc[qq * 4 + 2] = fmaf(w, ev.z, acc[qq * 4 + 2]);
                acc[qq * 4 + 3] = fmaf(w, ev.w, acc[qq * 4 + 3]);
            }
        }
        #pragma unroll
        for (int d = 0; d < 16; d += 2) {
            int k = hf * 16 + d;
            *(__half2*)(sAh + rowH * PG + k * 2) =
                __half2(__float2half_rn(acc[d]), __float2half_rn(acc[d + 1]));
        }
    }
    __syncthreads();                                   // B4: ag visible

    // ---- stage 5: p1 = lrelu(ag @ fW1 + c_f) (K=32) ----
    #pragma unroll
    for (int t = 0; t < 2; ++t)
        #pragma unroll
        for (int n = 0; n < 8; ++n)
            C[t][n][0] = C[t][n][1] = C[t][n][2] = C[t][n][3] = 0.f;
    gemm_2m<2, 4, PG, PF1>(uA + aOffG, smb + OFF_F1 + wOffF1, C);
    __syncthreads();                                   // B5a: ag reads done (cross-pair region overlap)
    #pragma unroll
    for (int t = 0; t < 2; ++t) {
        int ra = r0 + 16 * t, rb = ra + 8;
        const float* cfa = d_cf + (ra & 31) * 128;
        const float* cfb = d_cf + (rb & 31) * 128;
        #pragma unroll
        for (int nt = 0; nt < 8; ++nt) {
            int col = nc0 + nt * 8 + c2;
            float v0 = lrelu(C[t][nt][0] + __ldg(cfa + col));
            float v1 = lrelu(C[t][nt][1] + __ldg(cfa + col + 1));
            float v2 = lrelu(C[t][nt][2] + __ldg(cfb + col));
            float v3 = lrelu(C[t][nt][3] + __ldg(cfb + col + 1));
            *(__half2*)(sAh + ra * PA + col * 2) =
                __half2(__float2half_rn(v0), __float2half_rn(v1));
            *(__half2*)(sAh + rb * PA + col * 2) =
                __half2(__float2half_rn(v2), __float2half_rn(v3));
        }
    }
    BARP(pairid);                                      // B5b: p1 visible in pair

    // ---- stage 6: p1 @ fW2 ----
    #pragma unroll
    for (int t = 0; t < 2; ++t)
        #pragma unroll
        for (int n = 0; n < 8; ++n)
            C[t][n][0] = C[t][n][1] = C[t][n][2] = C[t][n][3] = 0.f;
    gemm_2m<8, 4, PA, PA>(uA + aOffA, smb + OFF_F2 + wOffA, C);

    // ---- stage 7a: p2 into C (read-only on sAh, no barrier needed) ----
    #pragma unroll
    for (int t = 0; t < 2; ++t) {
        int ra = r0 + 16 * t, rb = ra + 8;
        #pragma unroll
        for (int nt = 0; nt < 8; ++nt) {
            int col = nc0 + nt * 8 + c2;
            float b0 = __ldg(fb2 + col), b1 = __ldg(fb2 + col + 1);
            __half2 hh = *(__half2*)(sAh + ra * PA + col * 2);
            C[t][nt][0] = __half2float(hh.x) + lrelu(C[t][nt][0] + b0);
            C[t][nt][1] = __half2float(hh.y) + lrelu(C[t][nt][1] + b1);
            hh = *(__half2*)(sAh + rb * PA + col * 2);
            C[t][nt][2] = __half2float(hh.x) + lrelu(C[t][nt][2] + b0);
            C[t][nt][3] = __half2float(hh.y) + lrelu(C[t][nt][3] + b1);
        }
    }

    // ---- stage 7b: dot with fW3 (resident), reduce, partials ----
    {
        const float* sW3 = (const float*)(sm + OFF_F3);
        float acc[2][2] = {{0.f, 0.f}, {0.f, 0.f}};
        #pragma unroll
        for (int t = 0; t < 2; ++t) {
            int ra = r0 + 16 * t, rb = ra + 8;
            int ia = ra & 31, ib = rb & 31;
            #pragma unroll
            for (int nt = 0; nt < 8; ++nt) {
                int col = nc0 + nt * 8 + c2;
                acc[t][0] = fmaf(C[t][nt][0], sW3[col * PF3 + ia], acc[t][0]);
                acc[t][0] = fmaf(C[t][nt][1], sW3[(col + 1) * PF3 + ia], acc[t][0]);
                acc[t][1] = fmaf(C[t][nt][2], sW3[col * PF3 + ib], acc[t][1]);
                acc[t][1] = fmaf(C[t][nt][3], sW3[(col + 1) * PF3 + ib], acc[t][1]);
            }
        }
        #pragma unroll
        for (int t = 0; t < 2; ++t) {
            acc[t][0] += __shfl_xor_sync(0xffffffffu, acc[t][0], 1);
            acc[t][0] += __shfl_xor_sync(0xffffffffu, acc[t][0], 2);
            acc[t][1] += __shfl_xor_sync(0xffffffffu, acc[t][1], 1);
            acc[t][1] += __shfl_xor_sync(0xffffffffu, acc[t][1], 2);
        }
        __syncthreads();                               // B6: sPx reusable
        if ((lane & 3) == 0) {
            #pragma unroll
            for (int t = 0; t < 2; ++t) {
                sPx[nh * 256 + r0 + 16 * t]     = acc[t][0];
                sPx[nh * 256 + r0 + 16 * t + 8] = acc[t][1];
            }
        }
    }
    __syncthreads();                                   // B7: partials visible
    if (tid < 256)
        out[blockIdx.x * 256 + tid] = sPx[tid] + sPx[256 + tid] + __ldg(fb3 + (tid & 31));
}

// ---------------------------------------------------------------------------
extern "C" void kernel_launch(void* const* d_in, const int* in_sizes, int n_in,
                              void* d_out, int out_size) {
    const float* X   = (const float*)d_in[0];
    const float* W   = (const float*)d_in[1];
    const float* emb = (const float*)d_in[2];
    const float* gW1 = (const float*)d_in[3];
    const float* gb1 = (const float*)d_in[4];
    const float* gW2 = (const float*)d_in[5];
    const float* gb2 = (const float*)d_in[6];
    const float* gW3 = (const float*)d_in[7];
    const float* gb3 = (const float*)d_in[8];
    const float* fW1 = (const float*)d_in[9];
    const float* fb1 = (const float*)d_in[10];
    const float* fW2 = (const float*)d_in[11];
    const float* fb2 = (const float*)d_in[12];
    const float* fW3 = (const float*)d_in[13];
    const float* fb3 = (const float*)d_in[14];
    float* out = (float*)d_out;

    int B = in_sizes[0] / 32;

    cudaFuncSetAttribute(fused_gnn_kernel,
                         cudaFuncAttributeMaxDynamicSharedMemorySize, SMEM_BYTES);

    setup_kernel<<<160, 256>>>(W, emb, gW1, gb1, gW2, gW3, fW1, fb1, fW2);
    fused_gnn_kernel<<<B / 8, 512, SMEM_BYTES>>>(X, gW1, gb2, gb3, fb2, fW3, fb3, out);
}